// round 10
// baseline (speedup 1.0000x reference)
#include <cuda_runtime.h>
#include <cuda_bf16.h>
#include <cstdint>

#define B_     32
#define H_     2048
#define V_     128000
#define HIST_  2048
#define NT     128          // W rows per CTA
#define KC     64           // K chunk
#define NCHUNK (H_ / KC)    // 32
#define CAP    1024

// GEMM dynamic SMEM (R7-proven): A bufs @ 0/8192 (64r x 128B swizzled bf16),
// W bufs @ 16384 + i*34816 (128r x 272B padded fp32)
#define WSTRIDE_F 68
#define GEMM_SMEM (16384 + 2 * 34816)     // 86016

// select dynamic SMEM
#define SEL_SMEM  (32768 + 16000 + 8192 + 512)

// ---------------- device scratch ----------------
__device__ __nv_bfloat16 g_ahi[B_ * H_];
__device__ __nv_bfloat16 g_alo[B_ * H_];
__device__ float         g_logits[(size_t)B_ * V_];

// ---------------- helpers ----------------
__device__ __forceinline__ uint32_t smem_u32(const void* p) {
    uint32_t a;
    asm("{ .reg .u64 t; cvta.to.shared.u64 t, %1; cvt.u32.u64 %0, t; }" : "=r"(a) : "l"(p));
    return a;
}
#define SWZ(o) ((o) ^ (((o) >> 3) & 0x70))

#define CP16(dst, src) \
    asm volatile("cp.async.cg.shared.global [%0], [%1], 16;" :: "r"(dst), "l"(src))
#define CP_COMMIT() asm volatile("cp.async.commit_group;" ::: "memory")
#define CP_WAIT1()  asm volatile("cp.async.wait_group 1;" ::: "memory")

__device__ __forceinline__ uint32_t pack_bf16x2(float lo, float hi) {
    uint32_t r;
    asm("cvt.rn.bf16x2.f32 %0, %1, %2;" : "=r"(r) : "f"(hi), "f"(lo));
    return r;
}
__device__ __forceinline__ void ldmx4(uint32_t* r, uint32_t addr) {
    asm volatile("ldmatrix.sync.aligned.m8n8.x4.shared.b16 {%0,%1,%2,%3}, [%4];"
                 : "=r"(r[0]), "=r"(r[1]), "=r"(r[2]), "=r"(r[3]) : "r"(addr));
}
__device__ __forceinline__ void mma16816(float* d, const uint32_t* a,
                                         uint32_t b0, uint32_t b1) {
    asm volatile(
        "mma.sync.aligned.m16n8k16.row.col.f32.bf16.bf16.f32 "
        "{%0,%1,%2,%3}, {%4,%5,%6,%7}, {%8,%9}, {%0,%1,%2,%3};"
        : "+f"(d[0]), "+f"(d[1]), "+f"(d[2]), "+f"(d[3])
        : "r"(a[0]), "r"(a[1]), "r"(a[2]), "r"(a[3]), "r"(b0), "r"(b1));
}

// ---------------- K0: LayerNorm -> bf16 hi/lo ----------------
__global__ void __launch_bounds__(256) ln_kernel(const float* __restrict__ hs,
                                                 const float* __restrict__ gamma,
                                                 const float* __restrict__ beta) {
    __shared__ float sbuf[8];
    const int b = blockIdx.x, tid = threadIdx.x;
    const float* x = hs + (size_t)b * H_;

    float v[8];
#pragma unroll
    for (int i = 0; i < 8; i++) v[i] = x[i * 256 + tid];

    float s = 0.f;
#pragma unroll
    for (int i = 0; i < 8; i++) s += v[i];
#pragma unroll
    for (int off = 16; off >= 1; off >>= 1) s += __shfl_xor_sync(0xffffffffu, s, off);
    if ((tid & 31) == 0) sbuf[tid >> 5] = s;
    __syncthreads();
    if (tid == 0) {
        float t = 0.f;
        for (int i = 0; i < 8; i++) t += sbuf[i];
        sbuf[0] = t * (1.0f / H_);
    }
    __syncthreads();
    const float mean = sbuf[0];
    __syncthreads();

    float sq = 0.f;
#pragma unroll
    for (int i = 0; i < 8; i++) { float d = v[i] - mean; sq += d * d; }
#pragma unroll
    for (int off = 16; off >= 1; off >>= 1) sq += __shfl_xor_sync(0xffffffffu, sq, off);
    if ((tid & 31) == 0) sbuf[tid >> 5] = sq;
    __syncthreads();
    if (tid == 0) {
        float t = 0.f;
        for (int i = 0; i < 8; i++) t += sbuf[i];
        sbuf[0] = t * (1.0f / H_);
    }
    __syncthreads();
    const float rs = rsqrtf(sbuf[0] + 1e-5f);

#pragma unroll
    for (int i = 0; i < 8; i++) {
        const int k = i * 256 + tid;
        const float h = (v[i] - mean) * rs * gamma[k] + beta[k];
        const __nv_bfloat16 hi = __float2bfloat16(h);
        g_ahi[b * H_ + k] = hi;
        g_alo[b * H_ + k] = __float2bfloat16(h - __bfloat162float(hi));
    }
}

// ---------------- K1: pipelined bf16 split GEMM (R7 config: 2-stage, 2 CTA/SM) ----------------
__global__ void __launch_bounds__(256, 2) gemm_mma(const float* __restrict__ W) {
    extern __shared__ __align__(16) char smem[];
    const uint32_t sb = smem_u32(smem);

    const int tid  = threadIdx.x;
    const int lane = tid & 31;
    const int wid  = tid >> 5;
    const int wn   = wid * 16;
    const int v0   = blockIdx.x * NT;

    float d1[4][2][4];
    float d2[2][2][4];
#pragma unroll
    for (int mt = 0; mt < 4; mt++)
#pragma unroll
        for (int nt = 0; nt < 2; nt++)
#pragma unroll
            for (int i = 0; i < 4; i++) d1[mt][nt][i] = 0.f;
#pragma unroll
    for (int mt = 0; mt < 2; mt++)
#pragma unroll
        for (int nt = 0; nt < 2; nt++)
#pragma unroll
            for (int i = 0; i < 4; i++) d2[mt][nt][i] = 0.f;

    const int arow = lane & 15;
    const int koff = (lane & 16) ? 8 : 0;
    const int brow = wn + (lane >> 2);
    const int bk   = (lane & 3) * 2;

    auto stage = [&](int c) {
        const int buf = c & 1;
        const int k0  = c * KC;
        const uint32_t ab = sb + buf * 8192;
        const uint32_t wb = sb + 16384 + buf * 34816;
#pragma unroll
        for (int i = tid; i < 512; i += 256) {
            const int r = i >> 3, q = i & 7;
            const void* src = (r < 32) ? (const void*)&g_ahi[r * H_ + k0 + q * 8]
                                       : (const void*)&g_alo[(r - 32) * H_ + k0 + q * 8];
            CP16(ab + SWZ(r * 128 + q * 16), src);
        }
#pragma unroll
        for (int i = tid; i < 2048; i += 256) {
            const int r = i >> 4, q = i & 15;
            CP16(wb + r * 272 + q * 16, W + (size_t)(v0 + r) * H_ + k0 + q * 4);
        }
    };

    stage(0);
    CP_COMMIT();

    for (int c = 0; c < NCHUNK; c++) {
        if (c + 1 < NCHUNK) stage(c + 1);
        CP_COMMIT();
        CP_WAIT1();
        __syncthreads();

        const int buf = c & 1;
        const uint32_t sA = sb + buf * 8192;
        const float* Wb = reinterpret_cast<const float*>(smem + 16384 + buf * 34816);

#pragma unroll
        for (int ks = 0; ks < 4; ks++) {
            const int kc = ks * 16 + koff;
            uint32_t a[4][4];
#pragma unroll
            for (int mt = 0; mt < 4; mt++)
                ldmx4(a[mt], sA + SWZ((mt * 16 + arow) * 128 + kc * 2));

#pragma unroll
            for (int nt = 0; nt < 2; nt++) {
                const float* wr = Wb + (brow + nt * 8) * WSTRIDE_F + ks * 16 + bk;
                const float2 w0 = *reinterpret_cast<const float2*>(wr);
                const float2 w1 = *reinterpret_cast<const float2*>(wr + 8);

                const uint32_t bh0 = pack_bf16x2(w0.x, w0.y);
                const uint32_t bh1 = pack_bf16x2(w1.x, w1.y);
                const float r0 = w0.x - __uint_as_float(bh0 << 16);
                const float r1 = w0.y - __uint_as_float(bh0 & 0xFFFF0000u);
                const float r2 = w1.x - __uint_as_float(bh1 << 16);
                const float r3 = w1.y - __uint_as_float(bh1 & 0xFFFF0000u);
                const uint32_t bl0 = pack_bf16x2(r0, r1);
                const uint32_t bl1 = pack_bf16x2(r2, r3);

#pragma unroll
                for (int mt = 0; mt < 4; mt++)
                    mma16816(d1[mt][nt], a[mt], bh0, bh1);
#pragma unroll
                for (int mt = 0; mt < 2; mt++)
                    mma16816(d2[mt][nt], a[mt], bl0, bl1);
            }
        }
        __syncthreads();
    }

#pragma unroll
    for (int mt = 0; mt < 2; mt++)
#pragma unroll
        for (int nt = 0; nt < 2; nt++)
#pragma unroll
            for (int hf = 0; hf < 2; hf++) {
                const int b = mt * 16 + (lane >> 2) + hf * 8;
                const int v = v0 + wn + nt * 8 + (lane & 3) * 2;
                const float x0 = d1[mt][nt][hf * 2]     + d1[mt + 2][nt][hf * 2] +
                                 d2[mt][nt][hf * 2];
                const float x1 = d1[mt][nt][hf * 2 + 1] + d1[mt + 2][nt][hf * 2 + 1] +
                                 d2[mt][nt][hf * 2 + 1];
                *reinterpret_cast<float2*>(&g_logits[(size_t)b * V_ + v]) =
                    make_float2(x0, x1);
            }
}

// ---------------- K2: fused penalty + top-50 + top-p ----------------
__device__ __forceinline__ float apply_pen(float x, const unsigned* bm, int i) {
    if ((bm[i >> 5] >> (i & 31)) & 1u) x = (x < 0.f) ? x * 1.1f : x / 1.1f;
    return x;
}
__device__ __forceinline__ unsigned mono_key(float x) {
    const unsigned u = __float_as_uint(x);
    return (u & 0x80000000u) ? ~u : (u | 0x80000000u);
}
// warp-aggregated histogram add: one atomic per distinct bin per warp
__device__ __forceinline__ void hist_add(unsigned* hist, unsigned bin) {
    const unsigned mask = __match_any_sync(0xffffffffu, bin);
    const int leader = __ffs(mask) - 1;
    if ((int)(threadIdx.x & 31) == leader)
        atomicAdd(&hist[bin], (unsigned)__popc(mask));
}

__global__ void __launch_bounds__(1024, 1) select_kernel(const int* __restrict__ ids,
                                                         float* __restrict__ out,
                                                         int out_size) {
    extern __shared__ __align__(16) char ssel[];
    unsigned int* hist = reinterpret_cast<unsigned int*>(ssel);            // 8192
    unsigned int* bm   = reinterpret_cast<unsigned int*>(ssel + 32768);    // 4000
    unsigned long long* cand = reinterpret_cast<unsigned long long*>(ssel + 48768); // 1024
    unsigned long long* sel  = reinterpret_cast<unsigned long long*>(ssel + 56960); // 50
    __shared__ int s_cnt, s_tbin;

    const int b = blockIdx.x, tid = threadIdx.x;
    const float* row = g_logits + (size_t)b * V_;

    for (int i = tid; i < 8192; i += 1024) hist[i] = 0u;
    for (int i = tid; i < 4000; i += 1024) bm[i] = 0u;
    if (tid == 0) s_cnt = 0;
    __syncthreads();

    for (int i = tid; i < HIST_; i += 1024) {
        const int v = ids[b * HIST_ + i];
        if ((unsigned)v < (unsigned)V_) atomicOr(&bm[v >> 5], 1u << (v & 31));
    }
    __syncthreads();

    // sweep 1: histogram of penalized values (vectorized + warp-aggregated)
    for (int i4 = tid; i4 < V_ / 4; i4 += 1024) {
        const float4 xv = *reinterpret_cast<const float4*>(row + i4 * 4);
        const int i0 = i4 * 4;
        hist_add(hist, mono_key(apply_pen(xv.x, bm, i0))     >> 19);
        hist_add(hist, mono_key(apply_pen(xv.y, bm, i0 + 1)) >> 19);
        hist_add(hist, mono_key(apply_pen(xv.z, bm, i0 + 2)) >> 19);
        hist_add(hist, mono_key(apply_pen(xv.w, bm, i0 + 3)) >> 19);
    }
    __syncthreads();

    if (tid == 0) {
        unsigned cum = 0;
        int t = 0;
        for (int bin = 8191; bin >= 0; bin--) {
            cum += hist[bin];
            if (cum >= 50u) { t = bin; break; }
        }
        s_tbin = t;
    }
    __syncthreads();

    // sweep 2: collect candidates
    const unsigned tkey = ((unsigned)s_tbin) << 19;
    for (int i4 = tid; i4 < V_ / 4; i4 += 1024) {
        const float4 xv = *reinterpret_cast<const float4*>(row + i4 * 4);
        const float xs[4] = {xv.x, xv.y, xv.z, xv.w};
#pragma unroll
        for (int j = 0; j < 4; j++) {
            const int i = i4 * 4 + j;
            const unsigned key = mono_key(apply_pen(xs[j], bm, i));
            if (key >= tkey) {
                const int pos = atomicAdd(&s_cnt, 1);
                if (pos < CAP)
                    cand[pos] = ((unsigned long long)key << 32) |
                                (unsigned)(0xffffffffu - i);
            }
        }
    }
    __syncthreads();
    const int cnt = (s_cnt < CAP) ? s_cnt : CAP;

    if (tid < 32) {
        for (int r = 0; r < 50; r++) {
            unsigned long long best = 0ull;
            int bidx = -1;
            for (int i = tid; i < cnt; i += 32)
                if (cand[i] > best) { best = cand[i]; bidx = i; }
#pragma unroll
            for (int off = 16; off >= 1; off >>= 1) {
                const unsigned long long ob = __shfl_xor_sync(0xffffffffu, best, off);
                const int oi = __shfl_xor_sync(0xffffffffu, bidx, off);
                if (ob > best) { best = ob; bidx = oi; }
            }
            if (tid == 0 && bidx >= 0) { sel[r] = best; cand[bidx] = 0ull; }
            __syncwarp();
        }
    }
    __syncthreads();

    if (tid == 0) {
        float vals[50];
        int   tok[50];
        for (int i = 0; i < 50; i++) {
            const unsigned long long k64 = sel[i];
            const unsigned key = (unsigned)(k64 >> 32);
            vals[i] = (key & 0x80000000u) ? __uint_as_float(key ^ 0x80000000u)
                                          : __uint_as_float(~key);
            tok[i] = (int)(0xffffffffu - (unsigned)(k64 & 0xffffffffu));
        }
        const float m = vals[0];
        float e[50], ssum = 0.f;
        for (int i = 0; i < 50; i++) { e[i] = expf(vals[i] - m); ssum += e[i]; }
        float cum = 0.f, filt[50];
        for (int i = 0; i < 50; i++) {
            cum += e[i] / ssum;
            const bool keep = (cum < 0.8f) || (i < 5);
            filt[i] = keep ? vals[i] : -1000.0f;
        }
        float m2 = filt[0];
        for (int i = 1; i < 50; i++) m2 = fmaxf(m2, filt[i]);
        float s2 = 0.f;
        for (int i = 0; i < 50; i++) s2 += expf(filt[i] - m2);
        const int toff = out_size >> 1;
        for (int i = 0; i < 50; i++) {
            out[b * 50 + i] = expf(filt[i] - m2) / s2;
            out[toff + b * 50 + i] = (float)tok[i];
        }
    }
}

// ---------------- launch ----------------
extern "C" void kernel_launch(void* const* d_in, const int* in_sizes, int n_in,
                              void* d_out, int out_size) {
    const int*   ids   = (const int*)d_in[0];
    const float* hs    = (const float*)d_in[1];
    const float* gamma = (const float*)d_in[2];
    const float* beta  = (const float*)d_in[3];
    const float* Wm    = (const float*)d_in[4];

    cudaFuncSetAttribute(gemm_mma, cudaFuncAttributeMaxDynamicSharedMemorySize, GEMM_SMEM);
    cudaFuncSetAttribute(select_kernel, cudaFuncAttributeMaxDynamicSharedMemorySize, SEL_SMEM);

    ln_kernel<<<B_, 256>>>(hs, gamma, beta);
    gemm_mma<<<V_ / NT, 256, GEMM_SMEM>>>(Wm);
    select_kernel<<<B_, 1024, SEL_SMEM>>>(ids, (float*)d_out, out_size);
}

// round 11
// speedup vs baseline: 1.2185x; 1.2185x over previous
#include <cuda_runtime.h>
#include <cuda_bf16.h>
#include <cstdint>

#define B_     32
#define H_     2048
#define V_     128000
#define HIST_  2048
#define NT     128          // W rows per CTA
#define KC     64           // K chunk
#define NCHUNK (H_ / KC)    // 32
#define CAP    1024

// GEMM dynamic SMEM (R7-proven): A bufs @ 0/8192 (64r x 128B swizzled bf16),
// W bufs @ 16384 + i*34816 (128r x 272B padded fp32)
#define WSTRIDE_F 68
#define GEMM_SMEM (16384 + 2 * 34816)     // 86016

// ---------------- device scratch ----------------
__device__ __nv_bfloat16 g_ahi[B_ * H_];
__device__ __nv_bfloat16 g_alo[B_ * H_];
__device__ float         g_logits[(size_t)B_ * V_];

// ---------------- helpers ----------------
__device__ __forceinline__ uint32_t smem_u32(const void* p) {
    uint32_t a;
    asm("{ .reg .u64 t; cvta.to.shared.u64 t, %1; cvt.u32.u64 %0, t; }" : "=r"(a) : "l"(p));
    return a;
}
#define SWZ(o) ((o) ^ (((o) >> 3) & 0x70))

#define CP16(dst, src) \
    asm volatile("cp.async.cg.shared.global [%0], [%1], 16;" :: "r"(dst), "l"(src))
#define CP_COMMIT() asm volatile("cp.async.commit_group;" ::: "memory")
#define CP_WAIT1()  asm volatile("cp.async.wait_group 1;" ::: "memory")

__device__ __forceinline__ uint32_t pack_bf16x2(float lo, float hi) {
    uint32_t r;
    asm("cvt.rn.bf16x2.f32 %0, %1, %2;" : "=r"(r) : "f"(hi), "f"(lo));
    return r;
}
__device__ __forceinline__ void ldmx4(uint32_t* r, uint32_t addr) {
    asm volatile("ldmatrix.sync.aligned.m8n8.x4.shared.b16 {%0,%1,%2,%3}, [%4];"
                 : "=r"(r[0]), "=r"(r[1]), "=r"(r[2]), "=r"(r[3]) : "r"(addr));
}
__device__ __forceinline__ void mma16816(float* d, const uint32_t* a,
                                         uint32_t b0, uint32_t b1) {
    asm volatile(
        "mma.sync.aligned.m16n8k16.row.col.f32.bf16.bf16.f32 "
        "{%0,%1,%2,%3}, {%4,%5,%6,%7}, {%8,%9}, {%0,%1,%2,%3};"
        : "+f"(d[0]), "+f"(d[1]), "+f"(d[2]), "+f"(d[3])
        : "r"(a[0]), "r"(a[1]), "r"(a[2]), "r"(a[3]), "r"(b0), "r"(b1));
}

// ---------------- K0: LayerNorm -> bf16 hi/lo (R7-proven) ----------------
__global__ void __launch_bounds__(256) ln_kernel(const float* __restrict__ hs,
                                                 const float* __restrict__ gamma,
                                                 const float* __restrict__ beta) {
    __shared__ float sbuf[8];
    const int b = blockIdx.x, tid = threadIdx.x;
    const float* x = hs + (size_t)b * H_;

    float v[8];
#pragma unroll
    for (int i = 0; i < 8; i++) v[i] = x[i * 256 + tid];

    float s = 0.f;
#pragma unroll
    for (int i = 0; i < 8; i++) s += v[i];
#pragma unroll
    for (int off = 16; off >= 1; off >>= 1) s += __shfl_xor_sync(0xffffffffu, s, off);
    if ((tid & 31) == 0) sbuf[tid >> 5] = s;
    __syncthreads();
    if (tid == 0) {
        float t = 0.f;
        for (int i = 0; i < 8; i++) t += sbuf[i];
        sbuf[0] = t * (1.0f / H_);
    }
    __syncthreads();
    const float mean = sbuf[0];
    __syncthreads();

    float sq = 0.f;
#pragma unroll
    for (int i = 0; i < 8; i++) { float d = v[i] - mean; sq += d * d; }
#pragma unroll
    for (int off = 16; off >= 1; off >>= 1) sq += __shfl_xor_sync(0xffffffffu, sq, off);
    if ((tid & 31) == 0) sbuf[tid >> 5] = sq;
    __syncthreads();
    if (tid == 0) {
        float t = 0.f;
        for (int i = 0; i < 8; i++) t += sbuf[i];
        sbuf[0] = t * (1.0f / H_);
    }
    __syncthreads();
    const float rs = rsqrtf(sbuf[0] + 1e-5f);

#pragma unroll
    for (int i = 0; i < 8; i++) {
        const int k = i * 256 + tid;
        const float h = (v[i] - mean) * rs * gamma[k] + beta[k];
        const __nv_bfloat16 hi = __float2bfloat16(h);
        g_ahi[b * H_ + k] = hi;
        g_alo[b * H_ + k] = __float2bfloat16(h - __bfloat162float(hi));
    }
}

// ---------------- K1: pipelined bf16 split GEMM (R7-proven, untouched) ----------------
__global__ void __launch_bounds__(256, 2) gemm_mma(const float* __restrict__ W) {
    extern __shared__ __align__(16) char smem[];
    const uint32_t sb = smem_u32(smem);

    const int tid  = threadIdx.x;
    const int lane = tid & 31;
    const int wid  = tid >> 5;
    const int wn   = wid * 16;
    const int v0   = blockIdx.x * NT;

    float d1[4][2][4];
    float d2[2][2][4];
#pragma unroll
    for (int mt = 0; mt < 4; mt++)
#pragma unroll
        for (int nt = 0; nt < 2; nt++)
#pragma unroll
            for (int i = 0; i < 4; i++) d1[mt][nt][i] = 0.f;
#pragma unroll
    for (int mt = 0; mt < 2; mt++)
#pragma unroll
        for (int nt = 0; nt < 2; nt++)
#pragma unroll
            for (int i = 0; i < 4; i++) d2[mt][nt][i] = 0.f;

    const int arow = lane & 15;
    const int koff = (lane & 16) ? 8 : 0;
    const int brow = wn + (lane >> 2);
    const int bk   = (lane & 3) * 2;

    auto stage = [&](int c) {
        const int buf = c & 1;
        const int k0  = c * KC;
        const uint32_t ab = sb + buf * 8192;
        const uint32_t wb = sb + 16384 + buf * 34816;
#pragma unroll
        for (int i = tid; i < 512; i += 256) {
            const int r = i >> 3, q = i & 7;
            const void* src = (r < 32) ? (const void*)&g_ahi[r * H_ + k0 + q * 8]
                                       : (const void*)&g_alo[(r - 32) * H_ + k0 + q * 8];
            CP16(ab + SWZ(r * 128 + q * 16), src);
        }
#pragma unroll
        for (int i = tid; i < 2048; i += 256) {
            const int r = i >> 4, q = i & 15;
            CP16(wb + r * 272 + q * 16, W + (size_t)(v0 + r) * H_ + k0 + q * 4);
        }
    };

    stage(0);
    CP_COMMIT();

    for (int c = 0; c < NCHUNK; c++) {
        if (c + 1 < NCHUNK) stage(c + 1);
        CP_COMMIT();
        CP_WAIT1();
        __syncthreads();

        const int buf = c & 1;
        const uint32_t sA = sb + buf * 8192;
        const float* Wb = reinterpret_cast<const float*>(smem + 16384 + buf * 34816);

#pragma unroll
        for (int ks = 0; ks < 4; ks++) {
            const int kc = ks * 16 + koff;
            uint32_t a[4][4];
#pragma unroll
            for (int mt = 0; mt < 4; mt++)
                ldmx4(a[mt], sA + SWZ((mt * 16 + arow) * 128 + kc * 2));

#pragma unroll
            for (int nt = 0; nt < 2; nt++) {
                const float* wr = Wb + (brow + nt * 8) * WSTRIDE_F + ks * 16 + bk;
                const float2 w0 = *reinterpret_cast<const float2*>(wr);
                const float2 w1 = *reinterpret_cast<const float2*>(wr + 8);

                const uint32_t bh0 = pack_bf16x2(w0.x, w0.y);
                const uint32_t bh1 = pack_bf16x2(w1.x, w1.y);
                const float r0 = w0.x - __uint_as_float(bh0 << 16);
                const float r1 = w0.y - __uint_as_float(bh0 & 0xFFFF0000u);
                const float r2 = w1.x - __uint_as_float(bh1 << 16);
                const float r3 = w1.y - __uint_as_float(bh1 & 0xFFFF0000u);
                const uint32_t bl0 = pack_bf16x2(r0, r1);
                const uint32_t bl1 = pack_bf16x2(r2, r3);

#pragma unroll
                for (int mt = 0; mt < 4; mt++)
                    mma16816(d1[mt][nt], a[mt], bh0, bh1);
#pragma unroll
                for (int mt = 0; mt < 2; mt++)
                    mma16816(d2[mt][nt], a[mt], bl0, bl1);
            }
        }
        __syncthreads();
    }

#pragma unroll
    for (int mt = 0; mt < 2; mt++)
#pragma unroll
        for (int nt = 0; nt < 2; nt++)
#pragma unroll
            for (int hf = 0; hf < 2; hf++) {
                const int b = mt * 16 + (lane >> 2) + hf * 8;
                const int v = v0 + wn + nt * 8 + (lane & 3) * 2;
                const float x0 = d1[mt][nt][hf * 2]     + d1[mt + 2][nt][hf * 2] +
                                 d2[mt][nt][hf * 2];
                const float x1 = d1[mt][nt][hf * 2 + 1] + d1[mt + 2][nt][hf * 2 + 1] +
                                 d2[mt][nt][hf * 2 + 1];
                *reinterpret_cast<float2*>(&g_logits[(size_t)b * V_ + v]) =
                    make_float2(x0, x1);
            }
}

// ---------------- K2: fused penalty + windowed top-50 + top-p ----------------
__device__ __forceinline__ float apply_pen(float x, const unsigned* bm, int i) {
    if ((bm[i >> 5] >> (i & 31)) & 1u) x = (x < 0.f) ? x * 1.1f : x / 1.1f;
    return x;
}
__device__ __forceinline__ unsigned mono_key(float x) {
    const unsigned u = __float_as_uint(x);
    return (u & 0x80000000u) ? ~u : (u | 0x80000000u);
}

__global__ void __launch_bounds__(1024, 1) select_kernel(const int* __restrict__ ids,
                                                         float* __restrict__ out,
                                                         int out_size) {
    __shared__ unsigned hist[1024];
    __shared__ unsigned bm[4000];
    __shared__ unsigned long long cand[CAP];
    __shared__ unsigned long long sel[50];
    __shared__ float sred[32];
    __shared__ float s_max;
    __shared__ int s_cnt, s_tbin;

    const int b = blockIdx.x, tid = threadIdx.x;
    const int lane = tid & 31, wid = tid >> 5;
    const float* row = g_logits + (size_t)b * V_;

    for (int i = tid; i < 4000; i += 1024) bm[i] = 0u;
    if (tid == 0) s_cnt = 0;
    __syncthreads();
    for (int i = tid; i < HIST_; i += 1024) {
        const int v = ids[b * HIST_ + i];
        if ((unsigned)v < (unsigned)V_) atomicOr(&bm[v >> 5], 1u << (v & 31));
    }
    __syncthreads();

    // pass 1: row max of penalized values
    float m = -1e30f;
    for (int i4 = tid; i4 < V_ / 4; i4 += 1024) {
        const float4 xv = *reinterpret_cast<const float4*>(row + i4 * 4);
        const int i0 = i4 * 4;
        m = fmaxf(m, apply_pen(xv.x, bm, i0));
        m = fmaxf(m, apply_pen(xv.y, bm, i0 + 1));
        m = fmaxf(m, apply_pen(xv.z, bm, i0 + 2));
        m = fmaxf(m, apply_pen(xv.w, bm, i0 + 3));
    }
#pragma unroll
    for (int off = 16; off >= 1; off >>= 1) m = fmaxf(m, __shfl_xor_sync(0xffffffffu, m, off));
    if (lane == 0) sred[wid] = m;
    __syncthreads();
    if (tid == 0) {
        float M = sred[0];
        for (int i = 1; i < 32; i++) M = fmaxf(M, sred[i]);
        s_max = M;
    }
    __syncthreads();
    const float M = s_max;

    // windowed histogram: only elements within [M-w, M] touch atomics
    float w = 1.0f;
    int t;
    for (;;) {
        const float lo = M - w, scale = 1024.0f / w;
        hist[tid & 1023] = 0u;           // 1024 threads cover all bins (tid<1024)
        __syncthreads();
        for (int i4 = tid; i4 < V_ / 4; i4 += 1024) {
            const float4 xv = *reinterpret_cast<const float4*>(row + i4 * 4);
            const int i0 = i4 * 4;
            const float xs[4] = {apply_pen(xv.x, bm, i0),     apply_pen(xv.y, bm, i0 + 1),
                                 apply_pen(xv.z, bm, i0 + 2), apply_pen(xv.w, bm, i0 + 3)};
#pragma unroll
            for (int j = 0; j < 4; j++) {
                if (xs[j] >= lo) {
                    int bin = (int)((xs[j] - lo) * scale);
                    bin = bin > 1023 ? 1023 : bin;
                    atomicAdd(&hist[bin], 1u);
                }
            }
        }
        __syncthreads();
        if (tid == 0) {
            unsigned cum = 0;
            int tt = -1;
            for (int bin = 1023; bin >= 0; bin--) {
                cum += hist[bin];
                if (cum >= 50u) { tt = bin; break; }
            }
            s_tbin = tt;
        }
        __syncthreads();
        t = s_tbin;
        if (t >= 0) break;
        w *= 2.0f;
        __syncthreads();
    }

    // collect: same bin formula as histogram pass
    {
        const float lo = M - w, scale = 1024.0f / w;
        for (int i4 = tid; i4 < V_ / 4; i4 += 1024) {
            const float4 xv = *reinterpret_cast<const float4*>(row + i4 * 4);
            const int i0 = i4 * 4;
            const float xs[4] = {apply_pen(xv.x, bm, i0),     apply_pen(xv.y, bm, i0 + 1),
                                 apply_pen(xv.z, bm, i0 + 2), apply_pen(xv.w, bm, i0 + 3)};
#pragma unroll
            for (int j = 0; j < 4; j++) {
                if (xs[j] >= lo) {
                    int bin = (int)((xs[j] - lo) * scale);
                    bin = bin > 1023 ? 1023 : bin;
                    if (bin >= t) {
                        const int pos = atomicAdd(&s_cnt, 1);
                        if (pos < CAP)
                            cand[pos] = ((unsigned long long)mono_key(xs[j]) << 32) |
                                        (unsigned)(0xffffffffu - (i0 + j));
                    }
                }
            }
        }
    }
    __syncthreads();
    const int cnt = (s_cnt < CAP) ? s_cnt : CAP;

    if (tid < 32) {
        for (int r = 0; r < 50; r++) {
            unsigned long long best = 0ull;
            int bidx = -1;
            for (int i = tid; i < cnt; i += 32)
                if (cand[i] > best) { best = cand[i]; bidx = i; }
#pragma unroll
            for (int off = 16; off >= 1; off >>= 1) {
                const unsigned long long ob = __shfl_xor_sync(0xffffffffu, best, off);
                const int oi = __shfl_xor_sync(0xffffffffu, bidx, off);
                if (ob > best) { best = ob; bidx = oi; }
            }
            if (tid == 0 && bidx >= 0) { sel[r] = best; cand[bidx] = 0ull; }
            __syncwarp();
        }
    }
    __syncthreads();

    if (tid == 0) {
        float vals[50];
        int   tok[50];
        for (int i = 0; i < 50; i++) {
            const unsigned long long k64 = sel[i];
            const unsigned key = (unsigned)(k64 >> 32);
            vals[i] = (key & 0x80000000u) ? __uint_as_float(key ^ 0x80000000u)
                                          : __uint_as_float(~key);
            tok[i] = (int)(0xffffffffu - (unsigned)(k64 & 0xffffffffu));
        }
        const float m0 = vals[0];
        float e[50], ssum = 0.f;
        for (int i = 0; i < 50; i++) { e[i] = expf(vals[i] - m0); ssum += e[i]; }
        float cum = 0.f, filt[50];
        for (int i = 0; i < 50; i++) {
            cum += e[i] / ssum;
            const bool keep = (cum < 0.8f) || (i < 5);
            filt[i] = keep ? vals[i] : -1000.0f;
        }
        float m2 = filt[0];
        for (int i = 1; i < 50; i++) m2 = fmaxf(m2, filt[i]);
        float s2 = 0.f;
        for (int i = 0; i < 50; i++) s2 += expf(filt[i] - m2);
        const int toff = out_size >> 1;
        for (int i = 0; i < 50; i++) {
            out[b * 50 + i] = expf(filt[i] - m2) / s2;
            out[toff + b * 50 + i] = (float)tok[i];
        }
    }
}

// ---------------- launch ----------------
extern "C" void kernel_launch(void* const* d_in, const int* in_sizes, int n_in,
                              void* d_out, int out_size) {
    const int*   ids   = (const int*)d_in[0];
    const float* hs    = (const float*)d_in[1];
    const float* gamma = (const float*)d_in[2];
    const float* beta  = (const float*)d_in[3];
    const float* Wm    = (const float*)d_in[4];

    cudaFuncSetAttribute(gemm_mma, cudaFuncAttributeMaxDynamicSharedMemorySize, GEMM_SMEM);

    ln_kernel<<<B_, 256>>>(hs, gamma, beta);
    gemm_mma<<<V_ / NT, 256, GEMM_SMEM>>>(Wm);
    select_kernel<<<B_, 1024>>>(ids, (float*)d_out, out_size);
}